// round 3
// baseline (speedup 1.0000x reference)
#include <cuda_runtime.h>

#define N_NODES 100000
#define F 128
#define NE 1600000
#define BN_EPS 1e-5f

// Scratch (no allocations allowed) — __device__ globals.
__device__ float g_h[N_NODES * F];    // (1+eps)x + agg
__device__ float g_h1[N_NODES * F];   // after Linear1
__device__ float g_stats[2 * F];      // [0..127] sum, [128..255] sumsq
__device__ float g_ab[2 * F];         // [0..127] a = gamma*rsqrt(var+eps), [128..255] b = beta - mu*a
__device__ int   g_is64;              // 1 if edge_index stored as int64, 0 if int32

// -------------------- dtype detection for edge_index --------------------
// int64 little-endian values < 2^31: odd 32-bit words are all 0.
// int32 edge list: odd words are random node ids — all-zero is impossible.
__global__ void detect_kernel(const int* __restrict__ ei32) {
    if (threadIdx.x == 0 && blockIdx.x == 0) {
        int nz = 0;
        for (int i = 1; i < 256; i += 2) nz |= ei32[i];
        g_is64 = (nz == 0) ? 1 : 0;
    }
}

// -------------------- init: h = (1+eps)*x ; zero stats --------------------
__global__ void init_kernel(const float* __restrict__ x, const float* __restrict__ eps) {
    int tid = blockIdx.x * blockDim.x + threadIdx.x;
    float s = 1.0f + eps[0];
    const int total4 = N_NODES * F / 4;
    const float4* x4 = (const float4*)x;
    float4* h4 = (float4*)g_h;
    for (int i = tid; i < total4; i += gridDim.x * blockDim.x) {
        float4 v = x4[i];
        v.x *= s; v.y *= s; v.z *= s; v.w *= s;
        h4[i] = v;
    }
    if (tid < 2 * F) g_stats[tid] = 0.0f;
}

// -------------------- scatter: h[row] += x[col] (warp per edge) --------------------
__global__ void scatter_kernel(const void* __restrict__ ei_raw, const float* __restrict__ x) {
    int gw = (blockIdx.x * blockDim.x + threadIdx.x) >> 5;
    if (gw >= NE) return;
    int lane = threadIdx.x & 31;

    int dst, src;
    if (g_is64) {
        const long long* ei = (const long long*)ei_raw;
        dst = (int)ei[gw];
        src = (int)ei[NE + gw];
    } else {
        const int* ei = (const int*)ei_raw;
        dst = ei[gw];
        src = ei[NE + gw];
    }
    if ((unsigned)dst >= N_NODES || (unsigned)src >= N_NODES) return;

    const float4* xs = (const float4*)(x + (size_t)src * F);
    float4 v = xs[lane];
    float* hd = g_h + (size_t)dst * F + lane * 4;
    asm volatile("red.global.add.v4.f32 [%0], {%1, %2, %3, %4};"
                 :: "l"(hd), "f"(v.x), "f"(v.y), "f"(v.z), "f"(v.w) : "memory");
}

// -------------------- GEMM: out[r][c] = sum_k A'[r][k] * W[c][k] + bias[c] --------------------
// MODE 0: A' = A, also accumulate per-feature sum/sumsq of the output into g_stats
// MODE 1: A' = relu(A * g_ab[k] + g_ab[F+k])   (BN+ReLU folded into the load)
// Block: 256 threads (16x16), each thread computes an 8x8 tile; block tile = 128 rows x 128 cols.
template<int MODE>
__global__ __launch_bounds__(256) void gemm_kernel(
    const float* __restrict__ A, const float* __restrict__ W,
    const float* __restrict__ bias, float* __restrict__ out, int nrows)
{
    extern __shared__ float smem[];
    float (*sA)[132] = (float(*)[132])smem;                 // [k][row]
    float (*sB)[132] = (float(*)[132])(smem + 128 * 132);   // [k][col] = W[col][k]

    const int tid = threadIdx.x;
    const int row0 = blockIdx.x * 128;

    // Load W transposed into smem: sB[k][c] = W[c*128 + k] (coalesced global read)
    for (int idx = tid; idx < 128 * 128; idx += 256) {
        int c = idx >> 7, k = idx & 127;
        sB[k][c] = W[idx];
    }
    // Load A tile transposed (+ optional BN/ReLU transform)
    for (int idx = tid; idx < 128 * 128; idx += 256) {
        int r = idx >> 7, k = idx & 127;
        int gr = row0 + r;
        float v = 0.0f;
        if (gr < nrows) v = A[(size_t)gr * F + k];
        if (MODE == 1) {
            float a = g_ab[k], b = g_ab[F + k];
            v = fmaxf(fmaf(v, a, b), 0.0f);
            if (gr >= nrows) v = 0.0f;   // keep padded rows inert
        }
        sA[k][r] = v;
    }
    __syncthreads();

    const int tc = tid & 15;
    const int tr = tid >> 4;

    float acc[8][8];
#pragma unroll
    for (int i = 0; i < 8; i++)
#pragma unroll
        for (int j = 0; j < 8; j++) acc[i][j] = 0.0f;

#pragma unroll 8
    for (int k = 0; k < 128; ++k) {
        float4 a0 = *(const float4*)&sA[k][tr * 8];
        float4 a1 = *(const float4*)&sA[k][tr * 8 + 4];
        float4 b0 = *(const float4*)&sB[k][tc * 8];
        float4 b1 = *(const float4*)&sB[k][tc * 8 + 4];
        float av[8] = {a0.x, a0.y, a0.z, a0.w, a1.x, a1.y, a1.z, a1.w};
        float bv[8] = {b0.x, b0.y, b0.z, b0.w, b1.x, b1.y, b1.z, b1.w};
#pragma unroll
        for (int i = 0; i < 8; i++)
#pragma unroll
            for (int j = 0; j < 8; j++)
                acc[i][j] = fmaf(av[i], bv[j], acc[i][j]);
    }

    float bs[8];
#pragma unroll
    for (int j = 0; j < 8; j++) bs[j] = bias[tc * 8 + j];

    if (MODE == 0) {
        // write out + accumulate per-feature stats
        float psum[8], psq[8];
#pragma unroll
        for (int j = 0; j < 8; j++) { psum[j] = 0.0f; psq[j] = 0.0f; }

#pragma unroll
        for (int i = 0; i < 8; i++) {
            int gr = row0 + tr * 8 + i;
            if (gr < nrows) {
                float o[8];
#pragma unroll
                for (int j = 0; j < 8; j++) {
                    float v = acc[i][j] + bs[j];
                    o[j] = v;
                    psum[j] += v;
                    psq[j] = fmaf(v, v, psq[j]);
                }
                float4* op = (float4*)&out[(size_t)gr * F + tc * 8];
                op[0] = make_float4(o[0], o[1], o[2], o[3]);
                op[1] = make_float4(o[4], o[5], o[6], o[7]);
            }
        }

        __syncthreads();           // smem tiles no longer needed
        if (tid < 256) smem[tid] = 0.0f;   // [0..127] sum, [128..255] sumsq
        __syncthreads();
#pragma unroll
        for (int j = 0; j < 8; j++) {
            atomicAdd(&smem[tc * 8 + j], psum[j]);
            atomicAdd(&smem[F + tc * 8 + j], psq[j]);
        }
        __syncthreads();
        if (tid < 256) atomicAdd(&g_stats[tid], smem[tid]);
    } else {
#pragma unroll
        for (int i = 0; i < 8; i++) {
            int gr = row0 + tr * 8 + i;
            if (gr < nrows) {
                float4* op = (float4*)&out[(size_t)gr * F + tc * 8];
                op[0] = make_float4(acc[i][0] + bs[0], acc[i][1] + bs[1],
                                    acc[i][2] + bs[2], acc[i][3] + bs[3]);
                op[1] = make_float4(acc[i][4] + bs[4], acc[i][5] + bs[5],
                                    acc[i][6] + bs[6], acc[i][7] + bs[7]);
            }
        }
    }
}

// -------------------- BN params: fold stats + gamma/beta into a,b --------------------
__global__ void bnparams_kernel(const float* __restrict__ gamma, const float* __restrict__ beta) {
    int j = threadIdx.x;
    if (j < F) {
        float inv_n = 1.0f / (float)N_NODES;
        float mu = g_stats[j] * inv_n;
        float var = g_stats[F + j] * inv_n - mu * mu;
        float a = gamma[j] * rsqrtf(var + BN_EPS);
        g_ab[j] = a;
        g_ab[F + j] = fmaf(-mu, a, beta[j]);
    }
}

// -------------------- launch --------------------
extern "C" void kernel_launch(void* const* d_in, const int* in_sizes, int n_in,
                              void* d_out, int out_size) {
    const float* x     = (const float*)d_in[0];
    const void*  ei    = d_in[1];
    const float* eps   = (const float*)d_in[2];
    const float* W1    = (const float*)d_in[3];
    const float* b1    = (const float*)d_in[4];
    const float* gamma = (const float*)d_in[5];
    const float* beta  = (const float*)d_in[6];
    const float* W2    = (const float*)d_in[7];
    const float* b2    = (const float*)d_in[8];
    float* out = (float*)d_out;

    float *h_ptr, *h1_ptr;
    cudaGetSymbolAddress((void**)&h_ptr, g_h);
    cudaGetSymbolAddress((void**)&h1_ptr, g_h1);

    const int smem_bytes = 2 * 128 * 132 * sizeof(float);
    cudaFuncSetAttribute(gemm_kernel<0>, cudaFuncAttributeMaxDynamicSharedMemorySize, smem_bytes);
    cudaFuncSetAttribute(gemm_kernel<1>, cudaFuncAttributeMaxDynamicSharedMemorySize, smem_bytes);

    // 0) detect edge_index dtype (int32 vs int64)
    detect_kernel<<<1, 32>>>((const int*)ei);

    // 1) h = (1+eps)*x ; zero stats
    init_kernel<<<2048, 256>>>(x, eps);

    // 2) scatter-add neighbors: h[row] += x[col]  (warp per edge)
    scatter_kernel<<<(NE * 32) / 256, 256>>>(ei, x);

    // 3) h1 = h @ W1^T + b1 (+ stats)
    int gblocks = (N_NODES + 127) / 128;
    gemm_kernel<0><<<gblocks, 256, smem_bytes>>>(h_ptr, W1, b1, h1_ptr, N_NODES);

    // 4) fold BN params
    bnparams_kernel<<<1, 128>>>(gamma, beta);

    // 5) out = relu(bn(h1)) @ W2^T + b2
    gemm_kernel<1><<<gblocks, 256, smem_bytes>>>(h1_ptr, W2, b2, out, N_NODES);
}

// round 4
// speedup vs baseline: 1.1365x; 1.1365x over previous
#include <cuda_runtime.h>

#define N_NODES 100000
#define F 128
#define NE 1600000
#define BN_EPS 1e-5f

// Scratch (no allocations allowed) — __device__ globals.
__device__ float g_h[N_NODES * F];    // (1+eps)x + agg
__device__ float g_h1[N_NODES * F];   // after Linear1
__device__ float g_stats[2 * F];      // [0..127] sum, [128..255] sumsq
__device__ float g_ab[2 * F];         // [0..127] a = gamma*rsqrt(var+eps), [128..255] b = beta - mu*a
__device__ int   g_is64;              // 1 if edge_index stored as int64, 0 if int32

// -------------------- dtype detection for edge_index --------------------
__global__ void detect_kernel(const int* __restrict__ ei32) {
    if (threadIdx.x == 0 && blockIdx.x == 0) {
        int nz = 0;
        for (int i = 1; i < 256; i += 2) nz |= ei32[i];
        g_is64 = (nz == 0) ? 1 : 0;
    }
}

// -------------------- init: h = (1+eps)*x ; zero stats --------------------
__global__ void init_kernel(const float* __restrict__ x, const float* __restrict__ eps) {
    int tid = blockIdx.x * blockDim.x + threadIdx.x;
    float s = 1.0f + eps[0];
    const int total4 = N_NODES * F / 4;
    const float4* x4 = (const float4*)x;
    float4* h4 = (float4*)g_h;
    for (int i = tid; i < total4; i += gridDim.x * blockDim.x) {
        float4 v = x4[i];
        v.x *= s; v.y *= s; v.z *= s; v.w *= s;
        h4[i] = v;
    }
    if (tid < 2 * F) g_stats[tid] = 0.0f;
}

// -------------------- scatter: h[row] += x[col] (warp per edge) --------------------
__global__ void scatter_kernel(const void* __restrict__ ei_raw, const float* __restrict__ x) {
    int gw = (blockIdx.x * blockDim.x + threadIdx.x) >> 5;
    if (gw >= NE) return;
    int lane = threadIdx.x & 31;

    int dst, src;
    if (g_is64) {
        const long long* ei = (const long long*)ei_raw;
        dst = (int)ei[gw];
        src = (int)ei[NE + gw];
    } else {
        const int* ei = (const int*)ei_raw;
        dst = ei[gw];
        src = ei[NE + gw];
    }
    if ((unsigned)dst >= N_NODES || (unsigned)src >= N_NODES) return;

    const float4* xs = (const float4*)(x + (size_t)src * F);
    float4 v = xs[lane];
    float* hd = g_h + (size_t)dst * F + lane * 4;
    asm volatile("red.global.add.v4.f32 [%0], {%1, %2, %3, %4};"
                 :: "l"(hd), "f"(v.x), "f"(v.y), "f"(v.z), "f"(v.w) : "memory");
}

// -------------------- GEMM: out[r][c] = sum_k A'[r][k] * W[c][k] + bias[c] --------------------
// MODE 0: A' = A, also accumulate per-feature sum/sumsq of the output into g_stats
// MODE 1: A' = relu(A * g_ab[k] + g_ab[F+k])   (BN+ReLU folded into the load)
// Block: 256 threads, block tile 128 rows x 128 cols, 8x8 per thread.
// W tile (128x132) resident for the whole block; A streamed in two 64-K chunks
// -> smem ~101KB -> 2 blocks/SM (16 warps) for latency hiding.
#define KC 64
template<int MODE>
__global__ __launch_bounds__(256, 2) void gemm_kernel(
    const float* __restrict__ A, const float* __restrict__ W,
    const float* __restrict__ bias, float* __restrict__ out, int nrows)
{
    extern __shared__ float smem[];
    float (*sB)[132] = (float(*)[132])smem;                 // [k][col] = W[col][k], full K
    float (*sA)[132] = (float(*)[132])(smem + 128 * 132);   // [k][row], K-chunk of 64

    const int tid = threadIdx.x;
    const int row0 = blockIdx.x * 128;

    // Load W transposed into smem: sB[k][c] = W[c*128 + k]
    for (int idx = tid; idx < 128 * 128; idx += 256) {
        int c = idx >> 7, k = idx & 127;
        sB[k][c] = W[idx];
    }

    const int tc = tid & 15;
    const int tr = tid >> 4;

    float acc[8][8];
#pragma unroll
    for (int i = 0; i < 8; i++)
#pragma unroll
        for (int j = 0; j < 8; j++) acc[i][j] = 0.0f;

    for (int k0 = 0; k0 < 128; k0 += KC) {
        __syncthreads();   // protect sA from previous chunk's readers (and order after W load)
        // Load A chunk transposed (+ optional BN/ReLU transform): sA[k][r] = A'[row0+r][k0+k]
        for (int idx = tid; idx < 128 * KC; idx += 256) {
            int r = idx / KC, k = idx % KC;
            int gr = row0 + r;
            float v = 0.0f;
            if (gr < nrows) v = A[(size_t)gr * F + k0 + k];
            if (MODE == 1) {
                float a = g_ab[k0 + k], b = g_ab[F + k0 + k];
                v = fmaxf(fmaf(v, a, b), 0.0f);
                if (gr >= nrows) v = 0.0f;
            }
            sA[k][r] = v;
        }
        __syncthreads();

#pragma unroll 8
        for (int k = 0; k < KC; ++k) {
            float4 a0 = *(const float4*)&sA[k][tr * 8];
            float4 a1 = *(const float4*)&sA[k][tr * 8 + 4];
            float4 b0 = *(const float4*)&sB[k0 + k][tc * 8];
            float4 b1 = *(const float4*)&sB[k0 + k][tc * 8 + 4];
            float av[8] = {a0.x, a0.y, a0.z, a0.w, a1.x, a1.y, a1.z, a1.w};
            float bv[8] = {b0.x, b0.y, b0.z, b0.w, b1.x, b1.y, b1.z, b1.w};
#pragma unroll
            for (int i = 0; i < 8; i++)
#pragma unroll
                for (int j = 0; j < 8; j++)
                    acc[i][j] = fmaf(av[i], bv[j], acc[i][j]);
        }
    }

    float bs[8];
#pragma unroll
    for (int j = 0; j < 8; j++) bs[j] = bias[tc * 8 + j];

    if (MODE == 0) {
        float psum[8], psq[8];
#pragma unroll
        for (int j = 0; j < 8; j++) { psum[j] = 0.0f; psq[j] = 0.0f; }

#pragma unroll
        for (int i = 0; i < 8; i++) {
            int gr = row0 + tr * 8 + i;
            if (gr < nrows) {
                float o[8];
#pragma unroll
                for (int j = 0; j < 8; j++) {
                    float v = acc[i][j] + bs[j];
                    o[j] = v;
                    psum[j] += v;
                    psq[j] = fmaf(v, v, psq[j]);
                }
                float4* op = (float4*)&out[(size_t)gr * F + tc * 8];
                op[0] = make_float4(o[0], o[1], o[2], o[3]);
                op[1] = make_float4(o[4], o[5], o[6], o[7]);
            }
        }

        __syncthreads();           // smem tiles no longer needed
        if (tid < 256) smem[tid] = 0.0f;   // [0..127] sum, [128..255] sumsq
        __syncthreads();
#pragma unroll
        for (int j = 0; j < 8; j++) {
            atomicAdd(&smem[tc * 8 + j], psum[j]);
            atomicAdd(&smem[F + tc * 8 + j], psq[j]);
        }
        __syncthreads();
        if (tid < 256) atomicAdd(&g_stats[tid], smem[tid]);
    } else {
#pragma unroll
        for (int i = 0; i < 8; i++) {
            int gr = row0 + tr * 8 + i;
            if (gr < nrows) {
                float4* op = (float4*)&out[(size_t)gr * F + tc * 8];
                op[0] = make_float4(acc[i][0] + bs[0], acc[i][1] + bs[1],
                                    acc[i][2] + bs[2], acc[i][3] + bs[3]);
                op[1] = make_float4(acc[i][4] + bs[4], acc[i][5] + bs[5],
                                    acc[i][6] + bs[6], acc[i][7] + bs[7]);
            }
        }
    }
}

// -------------------- BN params: fold stats + gamma/beta into a,b --------------------
__global__ void bnparams_kernel(const float* __restrict__ gamma, const float* __restrict__ beta) {
    int j = threadIdx.x;
    if (j < F) {
        float inv_n = 1.0f / (float)N_NODES;
        float mu = g_stats[j] * inv_n;
        float var = g_stats[F + j] * inv_n - mu * mu;
        float a = gamma[j] * rsqrtf(var + BN_EPS);
        g_ab[j] = a;
        g_ab[F + j] = fmaf(-mu, a, beta[j]);
    }
}

// -------------------- launch --------------------
extern "C" void kernel_launch(void* const* d_in, const int* in_sizes, int n_in,
                              void* d_out, int out_size) {
    const float* x     = (const float*)d_in[0];
    const void*  ei    = d_in[1];
    const float* eps   = (const float*)d_in[2];
    const float* W1    = (const float*)d_in[3];
    const float* b1    = (const float*)d_in[4];
    const float* gamma = (const float*)d_in[5];
    const float* beta  = (const float*)d_in[6];
    const float* W2    = (const float*)d_in[7];
    const float* b2    = (const float*)d_in[8];
    float* out = (float*)d_out;

    float *h_ptr, *h1_ptr;
    cudaGetSymbolAddress((void**)&h_ptr, g_h);
    cudaGetSymbolAddress((void**)&h1_ptr, g_h1);

    const int smem_bytes = (128 * 132 + KC * 132) * sizeof(float);
    cudaFuncSetAttribute(gemm_kernel<0>, cudaFuncAttributeMaxDynamicSharedMemorySize, smem_bytes);
    cudaFuncSetAttribute(gemm_kernel<1>, cudaFuncAttributeMaxDynamicSharedMemorySize, smem_bytes);

    // 0) detect edge_index dtype (int32 vs int64)
    detect_kernel<<<1, 32>>>((const int*)ei);

    // 1) h = (1+eps)*x ; zero stats
    init_kernel<<<2048, 256>>>(x, eps);

    // 2) scatter-add neighbors: h[row] += x[col]  (warp per edge)
    scatter_kernel<<<(NE * 32) / 256, 256>>>(ei, x);

    // 3) h1 = h @ W1^T + b1 (+ stats)
    int gblocks = (N_NODES + 127) / 128;
    gemm_kernel<0><<<gblocks, 256, smem_bytes>>>(h_ptr, W1, b1, h1_ptr, N_NODES);

    // 4) fold BN params
    bnparams_kernel<<<1, 128>>>(gamma, beta);

    // 5) out = relu(bn(h1)) @ W2^T + b2
    gemm_kernel<1><<<gblocks, 256, smem_bytes>>>(h1_ptr, W2, b2, out, N_NODES);
}

// round 7
// speedup vs baseline: 1.1958x; 1.0522x over previous
#include <cuda_runtime.h>
#include <cuda_bf16.h>
#include <cstdint>

#define N_NODES 100000
#define F 128
#define NE 1600000
#define BN_EPS 1e-5f

// Scratch (no allocations allowed) — __device__ globals.
__device__ float g_h[N_NODES * F];    // (1+eps)x + agg
__device__ float g_h1[N_NODES * F];   // after Linear1
__device__ float g_stats[2 * F];      // [0..127] sum, [128..255] sumsq
__device__ float g_ab[2 * F];         // a = gamma*rsqrt(var+eps), b = beta - mu*a
__device__ int   g_is64;              // 1 if edge_index stored as int64, 0 if int32

// -------------------- dtype detection for edge_index --------------------
__global__ void detect_kernel(const int* __restrict__ ei32) {
    if (threadIdx.x == 0 && blockIdx.x == 0) {
        int nz = 0;
        for (int i = 1; i < 256; i += 2) nz |= ei32[i];
        g_is64 = (nz == 0) ? 1 : 0;
    }
}

// -------------------- init: h = (1+eps)*x ; zero stats --------------------
__global__ void init_kernel(const float* __restrict__ x, const float* __restrict__ eps) {
    int tid = blockIdx.x * blockDim.x + threadIdx.x;
    float s = 1.0f + eps[0];
    const int total4 = N_NODES * F / 4;
    const float4* x4 = (const float4*)x;
    float4* h4 = (float4*)g_h;
    for (int i = tid; i < total4; i += gridDim.x * blockDim.x) {
        float4 v = x4[i];
        v.x *= s; v.y *= s; v.z *= s; v.w *= s;
        h4[i] = v;
    }
    if (tid < 2 * F) g_stats[tid] = 0.0f;
}

// -------------------- scatter: h[row] += x[col] (warp per edge) --------------------
__global__ void scatter_kernel(const void* __restrict__ ei_raw, const float* __restrict__ x) {
    int gw = (blockIdx.x * blockDim.x + threadIdx.x) >> 5;
    if (gw >= NE) return;
    int lane = threadIdx.x & 31;

    int dst, src;
    if (g_is64) {
        const long long* ei = (const long long*)ei_raw;
        dst = (int)ei[gw];
        src = (int)ei[NE + gw];
    } else {
        const int* ei = (const int*)ei_raw;
        dst = ei[gw];
        src = ei[NE + gw];
    }
    if ((unsigned)dst >= N_NODES || (unsigned)src >= N_NODES) return;

    const float4* xs = (const float4*)(x + (size_t)src * F);
    float4 v = xs[lane];
    float* hd = g_h + (size_t)dst * F + lane * 4;
    asm volatile("red.global.add.v4.f32 [%0], {%1, %2, %3, %4};"
                 :: "l"(hd), "f"(v.x), "f"(v.y), "f"(v.z), "f"(v.w) : "memory");
}

// -------------------- HMMA helpers --------------------
__device__ __forceinline__ void mma_bf16(float* c, uint32_t a0, uint32_t a1, uint32_t a2, uint32_t a3,
                                         uint32_t b0, uint32_t b1) {
    asm volatile(
        "mma.sync.aligned.m16n8k16.row.col.f32.bf16.bf16.f32 "
        "{%0,%1,%2,%3}, {%4,%5,%6,%7}, {%8,%9}, {%0,%1,%2,%3};"
        : "+f"(c[0]), "+f"(c[1]), "+f"(c[2]), "+f"(c[3])
        : "r"(a0), "r"(a1), "r"(a2), "r"(a3), "r"(b0), "r"(b1));
}

// smem tile geometry: [128 rows][136 bf16] (272B row stride: 16B-aligned, conflict-free)
#define TSTRIDE 136
#define TILE_ELEMS (128 * TSTRIDE)

// -------------------- mma GEMM: out = A' @ W^T + bias --------------------
// MODE 0: A' = A; also accumulate per-feature sum/sumsq into g_stats
// MODE 1: A' = relu(A * ab[k] + ab[F+k])   (BN+ReLU folded into the A load)
// Split-bf16: D = Ah*Wh + Ah*Wl + Al*Wh  (fp32 register accum)
// Block: 256 threads = 8 warps (2x4); warp tile 64x32; block tile 128x128.
template<int MODE>
__global__ __launch_bounds__(256, 1) void gemm_mma_kernel(
    const float* __restrict__ A, const float* __restrict__ W,
    const float* __restrict__ bias, float* __restrict__ out, int nrows)
{
    extern __shared__ char smem[];
    __nv_bfloat16* sAh = (__nv_bfloat16*)smem;
    __nv_bfloat16* sAl = sAh + TILE_ELEMS;
    __nv_bfloat16* sBh = sAl + TILE_ELEMS;
    __nv_bfloat16* sBl = sBh + TILE_ELEMS;
    float* s_bias  = (float*)(sBl + TILE_ELEMS);
    float* s_ab    = s_bias + 128;
    float* s_stats = s_ab + 256;

    const int tid = threadIdx.x;
    const int wid = tid >> 5;
    const int lane = tid & 31;
    const int gid = lane >> 2;    // group id (row within 8)
    const int tig = lane & 3;     // thread in group (k/col pair)
    const int wr = wid >> 2;      // warp row (0-1)
    const int wc = wid & 3;       // warp col (0-3)
    const int rbase = blockIdx.x * 128;

    if (tid < 128) s_bias[tid] = bias[tid];
    if (MODE == 1 && tid < 256) s_ab[tid] = g_ab[tid];
    if (MODE == 0 && tid < 256) s_stats[tid] = 0.0f;
    __syncthreads();

    // ---- convert W -> sBh/sBl: row c, k contiguous ----
    for (int idx = tid; idx < 128 * 32; idx += 256) {
        int c = idx >> 5, q = idx & 31;
        int k = q * 4;
        float4 v = *(const float4*)&W[c * F + k];
        __nv_bfloat16 h0 = __float2bfloat16(v.x), h1 = __float2bfloat16(v.y);
        __nv_bfloat16 h2 = __float2bfloat16(v.z), h3 = __float2bfloat16(v.w);
        __nv_bfloat16 l0 = __float2bfloat16(v.x - __bfloat162float(h0));
        __nv_bfloat16 l1 = __float2bfloat16(v.y - __bfloat162float(h1));
        __nv_bfloat16 l2 = __float2bfloat16(v.z - __bfloat162float(h2));
        __nv_bfloat16 l3 = __float2bfloat16(v.w - __bfloat162float(h3));
        *(__nv_bfloat162*)&sBh[c * TSTRIDE + k]     = __nv_bfloat162(h0, h1);
        *(__nv_bfloat162*)&sBh[c * TSTRIDE + k + 2] = __nv_bfloat162(h2, h3);
        *(__nv_bfloat162*)&sBl[c * TSTRIDE + k]     = __nv_bfloat162(l0, l1);
        *(__nv_bfloat162*)&sBl[c * TSTRIDE + k + 2] = __nv_bfloat162(l2, l3);
    }
    // ---- convert A tile -> sAh/sAl (with MODE-1 BN+ReLU) ----
    for (int idx = tid; idx < 128 * 32; idx += 256) {
        int r = idx >> 5, q = idx & 31;
        int k = q * 4;
        int gr = rbase + r;
        float4 v = make_float4(0.f, 0.f, 0.f, 0.f);
        if (gr < nrows) {
            v = *(const float4*)&A[(size_t)gr * F + k];
            if (MODE == 1) {
                v.x = fmaxf(fmaf(v.x, s_ab[k + 0], s_ab[F + k + 0]), 0.0f);
                v.y = fmaxf(fmaf(v.y, s_ab[k + 1], s_ab[F + k + 1]), 0.0f);
                v.z = fmaxf(fmaf(v.z, s_ab[k + 2], s_ab[F + k + 2]), 0.0f);
                v.w = fmaxf(fmaf(v.w, s_ab[k + 3], s_ab[F + k + 3]), 0.0f);
            }
        }
        __nv_bfloat16 h0 = __float2bfloat16(v.x), h1 = __float2bfloat16(v.y);
        __nv_bfloat16 h2 = __float2bfloat16(v.z), h3 = __float2bfloat16(v.w);
        __nv_bfloat16 l0 = __float2bfloat16(v.x - __bfloat162float(h0));
        __nv_bfloat16 l1 = __float2bfloat16(v.y - __bfloat162float(h1));
        __nv_bfloat16 l2 = __float2bfloat16(v.z - __bfloat162float(h2));
        __nv_bfloat16 l3 = __float2bfloat16(v.w - __bfloat162float(h3));
        *(__nv_bfloat162*)&sAh[r * TSTRIDE + k]     = __nv_bfloat162(h0, h1);
        *(__nv_bfloat162*)&sAh[r * TSTRIDE + k + 2] = __nv_bfloat162(h2, h3);
        *(__nv_bfloat162*)&sAl[r * TSTRIDE + k]     = __nv_bfloat162(l0, l1);
        *(__nv_bfloat162*)&sAl[r * TSTRIDE + k + 2] = __nv_bfloat162(l2, l3);
    }
    __syncthreads();

    // ---- mainloop: 3 splits x 8 k-steps, 16 mma each ----
    float acc[4][4][4];
#pragma unroll
    for (int mi = 0; mi < 4; mi++)
#pragma unroll
        for (int ni = 0; ni < 4; ni++)
#pragma unroll
            for (int j = 0; j < 4; j++) acc[mi][ni][j] = 0.0f;

    const __nv_bfloat16* aTiles[3] = {sAh, sAh, sAl};
    const __nv_bfloat16* bTiles[3] = {sBh, sBl, sBh};

#pragma unroll
    for (int s = 0; s < 3; s++) {
        const __nv_bfloat16* sa = aTiles[s];
        const __nv_bfloat16* sb = bTiles[s];
#pragma unroll
        for (int ks = 0; ks < 8; ks++) {
            const int k0 = ks * 16;
            // A fragments: 4 row blocks of 16
            uint32_t af[4][4];
#pragma unroll
            for (int mi = 0; mi < 4; mi++) {
                int r0 = wr * 64 + mi * 16 + gid;
                const __nv_bfloat16* p = sa + r0 * TSTRIDE + k0 + tig * 2;
                af[mi][0] = *(const uint32_t*)p;                       // (r0,   k0..k7 pair)
                af[mi][1] = *(const uint32_t*)(p + 8 * TSTRIDE);       // (r0+8, k0..k7)
                af[mi][2] = *(const uint32_t*)(p + 8);                 // (r0,   k8..k15)
                af[mi][3] = *(const uint32_t*)(p + 8 * TSTRIDE + 8);   // (r0+8, k8..k15)
            }
            // B fragments: 4 n blocks of 8
            uint32_t bf[4][2];
#pragma unroll
            for (int ni = 0; ni < 4; ni++) {
                int c0 = wc * 32 + ni * 8 + gid;
                const __nv_bfloat16* p = sb + c0 * TSTRIDE + k0 + tig * 2;
                bf[ni][0] = *(const uint32_t*)p;
                bf[ni][1] = *(const uint32_t*)(p + 8);
            }
#pragma unroll
            for (int mi = 0; mi < 4; mi++)
#pragma unroll
                for (int ni = 0; ni < 4; ni++)
                    mma_bf16(acc[mi][ni], af[mi][0], af[mi][1], af[mi][2], af[mi][3],
                             bf[ni][0], bf[ni][1]);
        }
    }

    // ---- epilogue: bias, store, (stats) ----
    float bsv[4][2];
#pragma unroll
    for (int ni = 0; ni < 4; ni++) {
        int c = wc * 32 + ni * 8 + tig * 2;
        bsv[ni][0] = s_bias[c];
        bsv[ni][1] = s_bias[c + 1];
    }

    float colsum[4][2], colsq[4][2];
#pragma unroll
    for (int ni = 0; ni < 4; ni++) {
        colsum[ni][0] = colsum[ni][1] = 0.0f;
        colsq[ni][0] = colsq[ni][1] = 0.0f;
    }

#pragma unroll
    for (int mi = 0; mi < 4; mi++) {
        int r0 = rbase + wr * 64 + mi * 16 + gid;
        int r1 = r0 + 8;
        bool v0 = (r0 < nrows), v1 = (r1 < nrows);
#pragma unroll
        for (int ni = 0; ni < 4; ni++) {
            int c = wc * 32 + ni * 8 + tig * 2;
            float o0 = acc[mi][ni][0] + bsv[ni][0];
            float o1 = acc[mi][ni][1] + bsv[ni][1];
            float o2 = acc[mi][ni][2] + bsv[ni][0];
            float o3 = acc[mi][ni][3] + bsv[ni][1];
            if (v0) *(float2*)&out[(size_t)r0 * F + c] = make_float2(o0, o1);
            if (v1) *(float2*)&out[(size_t)r1 * F + c] = make_float2(o2, o3);
            if (MODE == 0) {
                if (v0) {
                    colsum[ni][0] += o0; colsum[ni][1] += o1;
                    colsq[ni][0] = fmaf(o0, o0, colsq[ni][0]);
                    colsq[ni][1] = fmaf(o1, o1, colsq[ni][1]);
                }
                if (v1) {
                    colsum[ni][0] += o2; colsum[ni][1] += o3;
                    colsq[ni][0] = fmaf(o2, o2, colsq[ni][0]);
                    colsq[ni][1] = fmaf(o3, o3, colsq[ni][1]);
                }
            }
        }
    }

    if (MODE == 0) {
        // reduce over the 8 gid values (lanes differing in bits 2,3,4)
#pragma unroll
        for (int ni = 0; ni < 4; ni++)
#pragma unroll
            for (int j = 0; j < 2; j++) {
                float s = colsum[ni][j], q = colsq[ni][j];
#pragma unroll
                for (int off = 4; off < 32; off <<= 1) {
                    s += __shfl_xor_sync(0xFFFFFFFFu, s, off);
                    q += __shfl_xor_sync(0xFFFFFFFFu, q, off);
                }
                if (gid == 0) {
                    int c = wc * 32 + ni * 8 + tig * 2 + j;
                    atomicAdd(&s_stats[c], s);
                    atomicAdd(&s_stats[128 + c], q);
                }
            }
        __syncthreads();
        if (tid < 256) atomicAdd(&g_stats[tid], s_stats[tid]);
    }
}

// -------------------- BN params: fold stats + gamma/beta into a,b --------------------
__global__ void bnparams_kernel(const float* __restrict__ gamma, const float* __restrict__ beta) {
    int j = threadIdx.x;
    if (j < F) {
        float inv_n = 1.0f / (float)N_NODES;
        float mu = g_stats[j] * inv_n;
        float var = g_stats[F + j] * inv_n - mu * mu;
        float a = gamma[j] * rsqrtf(var + BN_EPS);
        g_ab[j] = a;
        g_ab[F + j] = fmaf(-mu, a, beta[j]);
    }
}

// -------------------- launch --------------------
extern "C" void kernel_launch(void* const* d_in, const int* in_sizes, int n_in,
                              void* d_out, int out_size) {
    const float* x     = (const float*)d_in[0];
    const void*  ei    = d_in[1];
    const float* eps   = (const float*)d_in[2];
    const float* W1    = (const float*)d_in[3];
    const float* b1    = (const float*)d_in[4];
    const float* gamma = (const float*)d_in[5];
    const float* beta  = (const float*)d_in[6];
    const float* W2    = (const float*)d_in[7];
    const float* b2    = (const float*)d_in[8];
    float* out = (float*)d_out;

    float *h_ptr, *h1_ptr;
    cudaGetSymbolAddress((void**)&h_ptr, g_h);
    cudaGetSymbolAddress((void**)&h1_ptr, g_h1);

    const int smem_bytes = 4 * TILE_ELEMS * 2 + (128 + 256 + 256) * 4;
    cudaFuncSetAttribute(gemm_mma_kernel<0>, cudaFuncAttributeMaxDynamicSharedMemorySize, smem_bytes);
    cudaFuncSetAttribute(gemm_mma_kernel<1>, cudaFuncAttributeMaxDynamicSharedMemorySize, smem_bytes);

    // 0) detect edge_index dtype (int32 vs int64)
    detect_kernel<<<1, 32>>>((const int*)ei);

    // 1) h = (1+eps)*x ; zero stats
    init_kernel<<<2048, 256>>>(x, eps);

    // 2) scatter-add neighbors: h[row] += x[col]  (warp per edge)
    scatter_kernel<<<(NE * 32) / 256, 256>>>(ei, x);

    // 3) h1 = h @ W1^T + b1 (+ stats)   [mma.sync bf16 split]
    int gblocks = (N_NODES + 127) / 128;
    gemm_mma_kernel<0><<<gblocks, 256, smem_bytes>>>(h_ptr, W1, b1, h1_ptr, N_NODES);

    // 4) fold BN params
    bnparams_kernel<<<1, 128>>>(gamma, beta);

    // 5) out = relu(bn(h1)) @ W2^T + b2   [mma.sync bf16 split]
    gemm_mma_kernel<1><<<gblocks, 256, smem_bytes>>>(h1_ptr, W2, b2, out, N_NODES);
}

// round 10
// speedup vs baseline: 1.3081x; 1.0939x over previous
#include <cuda_runtime.h>
#include <cuda_bf16.h>
#include <cstdint>

#define N_NODES 100000
#define F 128
#define NE 1600000
#define BN_EPS 1e-5f

// Scratch (no allocations allowed) — __device__ globals.
__device__ float g_h[N_NODES * F];    // (1+eps)x + agg
__device__ float g_h1[N_NODES * F];   // after Linear1
__device__ float g_stats[2 * F];      // [0..127] sum, [128..255] sumsq
__device__ float g_ab[2 * F];         // a = gamma*rsqrt(var+eps), b = beta - mu*a
__device__ int   g_is64;              // 1 if edge_index stored as int64, 0 if int32

// -------------------- dtype detection for edge_index --------------------
__global__ void detect_kernel(const int* __restrict__ ei32) {
    if (threadIdx.x == 0 && blockIdx.x == 0) {
        int nz = 0;
        for (int i = 1; i < 256; i += 2) nz |= ei32[i];
        g_is64 = (nz == 0) ? 1 : 0;
    }
}

// -------------------- init: h = (1+eps)*x ; zero stats --------------------
__global__ void init_kernel(const float* __restrict__ x, const float* __restrict__ eps) {
    int tid = blockIdx.x * blockDim.x + threadIdx.x;
    float s = 1.0f + eps[0];
    const int total4 = N_NODES * F / 4;
    const float4* x4 = (const float4*)x;
    float4* h4 = (float4*)g_h;
    for (int i = tid; i < total4; i += gridDim.x * blockDim.x) {
        float4 v = x4[i];
        v.x *= s; v.y *= s; v.z *= s; v.w *= s;
        h4[i] = v;
    }
    if (tid < 2 * F) g_stats[tid] = 0.0f;
}

// -------------------- scatter: h[row] += x[col] (warp per edge) --------------------
__global__ void scatter_kernel(const void* __restrict__ ei_raw, const float* __restrict__ x) {
    int gw = (blockIdx.x * blockDim.x + threadIdx.x) >> 5;
    if (gw >= NE) return;
    int lane = threadIdx.x & 31;

    int dst, src;
    if (g_is64) {
        const long long* ei = (const long long*)ei_raw;
        dst = (int)ei[gw];
        src = (int)ei[NE + gw];
    } else {
        const int* ei = (const int*)ei_raw;
        dst = ei[gw];
        src = ei[NE + gw];
    }
    if ((unsigned)dst >= N_NODES || (unsigned)src >= N_NODES) return;

    const float4* xs = (const float4*)(x + (size_t)src * F);
    float4 v = xs[lane];
    float* hd = g_h + (size_t)dst * F + lane * 4;
    asm volatile("red.global.add.v4.f32 [%0], {%1, %2, %3, %4};"
                 :: "l"(hd), "f"(v.x), "f"(v.y), "f"(v.z), "f"(v.w) : "memory");
}

// -------------------- HMMA / ldmatrix helpers --------------------
__device__ __forceinline__ void mma_bf16(float* c, uint32_t a0, uint32_t a1, uint32_t a2, uint32_t a3,
                                         uint32_t b0, uint32_t b1) {
    asm volatile(
        "mma.sync.aligned.m16n8k16.row.col.f32.bf16.bf16.f32 "
        "{%0,%1,%2,%3}, {%4,%5,%6,%7}, {%8,%9}, {%0,%1,%2,%3};"
        : "+f"(c[0]), "+f"(c[1]), "+f"(c[2]), "+f"(c[3])
        : "r"(a0), "r"(a1), "r"(a2), "r"(a3), "r"(b0), "r"(b1));
}
#define LDSM_X4(r0, r1, r2, r3, addr) \
    asm volatile("ldmatrix.sync.aligned.m8n8.x4.shared.b16 {%0,%1,%2,%3}, [%4];" \
                 : "=r"(r0), "=r"(r1), "=r"(r2), "=r"(r3) : "r"(addr))

__device__ __forceinline__ uint32_t smem_u32(const void* p) {
    uint32_t a;
    asm("{ .reg .u64 t; cvta.to.shared.u64 t, %1; cvt.u32.u64 %0, t; }" : "=r"(a) : "l"(p));
    return a;
}

// smem tile geometry: [128 rows][136 bf16] (272B row stride: 16B-aligned, conflict-free)
#define TSTRIDE 136
#define TILE_ELEMS (128 * TSTRIDE)

// -------------------- mma GEMM: out = A' @ W^T + bias --------------------
// MODE 0: A' = A; also accumulate per-feature sum/sumsq into g_stats
// MODE 1: A' = relu(A * ab[k] + ab[F+k])   (BN+ReLU folded into the A load)
// Split-bf16: D = Ah*Wh + Ah*Wl + Al*Wh  (fp32 register accum)
// Block: 512 threads = 16 warps (4x4); warp tile 32x32; block tile 128x128.
template<int MODE>
__global__ __launch_bounds__(512, 1) void gemm_mma_kernel(
    const float* __restrict__ A, const float* __restrict__ W,
    const float* __restrict__ bias, float* __restrict__ out, int nrows)
{
    extern __shared__ char smem[];
    __nv_bfloat16* sAh = (__nv_bfloat16*)smem;
    __nv_bfloat16* sAl = sAh + TILE_ELEMS;
    __nv_bfloat16* sBh = sAl + TILE_ELEMS;
    __nv_bfloat16* sBl = sBh + TILE_ELEMS;
    float* s_bias  = (float*)(sBl + TILE_ELEMS);
    float* s_ab    = s_bias + 128;
    float* s_stats = s_ab + 256;

    const int tid = threadIdx.x;
    const int wid = tid >> 5;
    const int lane = tid & 31;
    const int gid = lane >> 2;    // group id (row within 8)
    const int tig = lane & 3;     // thread in group
    const int wr = wid >> 2;      // warp row (0-3), 32 rows each
    const int wc = wid & 3;       // warp col (0-3), 32 cols each
    const int rbase = blockIdx.x * 128;

    if (tid < 128) s_bias[tid] = bias[tid];
    if (MODE == 1 && tid < 256) s_ab[tid] = g_ab[tid];
    if (MODE == 0 && tid < 256) s_stats[tid] = 0.0f;
    __syncthreads();

    // ---- convert W -> sBh/sBl: row c, k contiguous ----
    for (int idx = tid; idx < 128 * 32; idx += 512) {
        int c = idx >> 5, q = idx & 31;
        int k = q * 4;
        float4 v = *(const float4*)&W[c * F + k];
        __nv_bfloat16 h0 = __float2bfloat16(v.x), h1 = __float2bfloat16(v.y);
        __nv_bfloat16 h2 = __float2bfloat16(v.z), h3 = __float2bfloat16(v.w);
        __nv_bfloat16 l0 = __float2bfloat16(v.x - __bfloat162float(h0));
        __nv_bfloat16 l1 = __float2bfloat16(v.y - __bfloat162float(h1));
        __nv_bfloat16 l2 = __float2bfloat16(v.z - __bfloat162float(h2));
        __nv_bfloat16 l3 = __float2bfloat16(v.w - __bfloat162float(h3));
        *(__nv_bfloat162*)&sBh[c * TSTRIDE + k]     = __nv_bfloat162(h0, h1);
        *(__nv_bfloat162*)&sBh[c * TSTRIDE + k + 2] = __nv_bfloat162(h2, h3);
        *(__nv_bfloat162*)&sBl[c * TSTRIDE + k]     = __nv_bfloat162(l0, l1);
        *(__nv_bfloat162*)&sBl[c * TSTRIDE + k + 2] = __nv_bfloat162(l2, l3);
    }
    // ---- convert A tile -> sAh/sAl (with MODE-1 BN+ReLU) ----
    for (int idx = tid; idx < 128 * 32; idx += 512) {
        int r = idx >> 5, q = idx & 31;
        int k = q * 4;
        int gr = rbase + r;
        float4 v = make_float4(0.f, 0.f, 0.f, 0.f);
        if (gr < nrows) {
            v = *(const float4*)&A[(size_t)gr * F + k];
            if (MODE == 1) {
                v.x = fmaxf(fmaf(v.x, s_ab[k + 0], s_ab[F + k + 0]), 0.0f);
                v.y = fmaxf(fmaf(v.y, s_ab[k + 1], s_ab[F + k + 1]), 0.0f);
                v.z = fmaxf(fmaf(v.z, s_ab[k + 2], s_ab[F + k + 2]), 0.0f);
                v.w = fmaxf(fmaf(v.w, s_ab[k + 3], s_ab[F + k + 3]), 0.0f);
            }
        }
        __nv_bfloat16 h0 = __float2bfloat16(v.x), h1 = __float2bfloat16(v.y);
        __nv_bfloat16 h2 = __float2bfloat16(v.z), h3 = __float2bfloat16(v.w);
        __nv_bfloat16 l0 = __float2bfloat16(v.x - __bfloat162float(h0));
        __nv_bfloat16 l1 = __float2bfloat16(v.y - __bfloat162float(h1));
        __nv_bfloat16 l2 = __float2bfloat16(v.z - __bfloat162float(h2));
        __nv_bfloat16 l3 = __float2bfloat16(v.w - __bfloat162float(h3));
        *(__nv_bfloat162*)&sAh[r * TSTRIDE + k]     = __nv_bfloat162(h0, h1);
        *(__nv_bfloat162*)&sAh[r * TSTRIDE + k + 2] = __nv_bfloat162(h2, h3);
        *(__nv_bfloat162*)&sAl[r * TSTRIDE + k]     = __nv_bfloat162(l0, l1);
        *(__nv_bfloat162*)&sAl[r * TSTRIDE + k + 2] = __nv_bfloat162(l2, l3);
    }
    __syncthreads();

    // ---- per-lane ldmatrix offsets (elements) ----
    // A (.x4): tiles = (m0-7,k0-7), (m8-15,k0-7), (m0-7,k8-15), (m8-15,k8-15)
    const int a_off = (((lane >> 3) & 1) * 8 + (lane & 7)) * TSTRIDE + ((lane >> 4) & 1) * 8;
    // B (.x4): tiles = (n0-7,k0-7), (n0-7,k8-15), (n8-15,k0-7), (n8-15,k8-15)
    const int b_off = (((lane >> 4) & 1) * 8 + (lane & 7)) * TSTRIDE + ((lane >> 3) & 1) * 8;

    const uint32_t sAh_u = smem_u32(sAh), sAl_u = smem_u32(sAl);
    const uint32_t sBh_u = smem_u32(sBh), sBl_u = smem_u32(sBl);

    // ---- mainloop: 3 splits x 8 k-steps; per k-step: 2 A-ldsm + 2 B-ldsm + 8 mma ----
    float acc[2][4][4];
#pragma unroll
    for (int mi = 0; mi < 2; mi++)
#pragma unroll
        for (int ni = 0; ni < 4; ni++)
#pragma unroll
            for (int j = 0; j < 4; j++) acc[mi][ni][j] = 0.0f;

    const uint32_t aBase[3] = {sAh_u, sAh_u, sAl_u};
    const uint32_t bBase[3] = {sBh_u, sBl_u, sBh_u};

#pragma unroll
    for (int s = 0; s < 3; s++) {
        const uint32_t sa = aBase[s] + 2 * (wr * 32 * TSTRIDE + a_off);
        const uint32_t sb = bBase[s] + 2 * (wc * 32 * TSTRIDE + b_off);
#pragma unroll
        for (int ks = 0; ks < 8; ks++) {
            const uint32_t kb = 2 * (ks * 16);
            uint32_t af[2][4];
            LDSM_X4(af[0][0], af[0][1], af[0][2], af[0][3], sa + kb);
            LDSM_X4(af[1][0], af[1][1], af[1][2], af[1][3], sa + 2 * (16 * TSTRIDE) + kb);
            uint32_t bf[4][2];
            LDSM_X4(bf[0][0], bf[0][1], bf[1][0], bf[1][1], sb + kb);
            LDSM_X4(bf[2][0], bf[2][1], bf[3][0], bf[3][1], sb + 2 * (16 * TSTRIDE) + kb);
#pragma unroll
            for (int mi = 0; mi < 2; mi++)
#pragma unroll
                for (int ni = 0; ni < 4; ni++)
                    mma_bf16(acc[mi][ni], af[mi][0], af[mi][1], af[mi][2], af[mi][3],
                             bf[ni][0], bf[ni][1]);
        }
    }

    // ---- epilogue: bias, store, (stats) ----
    float bsv[4][2];
#pragma unroll
    for (int ni = 0; ni < 4; ni++) {
        int c = wc * 32 + ni * 8 + tig * 2;
        bsv[ni][0] = s_bias[c];
        bsv[ni][1] = s_bias[c + 1];
    }

    float colsum[4][2], colsq[4][2];
#pragma unroll
    for (int ni = 0; ni < 4; ni++) {
        colsum[ni][0] = colsum[ni][1] = 0.0f;
        colsq[ni][0] = colsq[ni][1] = 0.0f;
    }

#pragma unroll
    for (int mi = 0; mi < 2; mi++) {
        int r0 = rbase + wr * 32 + mi * 16 + gid;
        int r1 = r0 + 8;
        bool v0 = (r0 < nrows), v1 = (r1 < nrows);
#pragma unroll
        for (int ni = 0; ni < 4; ni++) {
            int c = wc * 32 + ni * 8 + tig * 2;
            float o0 = acc[mi][ni][0] + bsv[ni][0];
            float o1 = acc[mi][ni][1] + bsv[ni][1];
            float o2 = acc[mi][ni][2] + bsv[ni][0];
            float o3 = acc[mi][ni][3] + bsv[ni][1];
            if (v0) *(float2*)&out[(size_t)r0 * F + c] = make_float2(o0, o1);
            if (v1) *(float2*)&out[(size_t)r1 * F + c] = make_float2(o2, o3);
            if (MODE == 0) {
                if (v0) {
                    colsum[ni][0] += o0; colsum[ni][1] += o1;
                    colsq[ni][0] = fmaf(o0, o0, colsq[ni][0]);
                    colsq[ni][1] = fmaf(o1, o1, colsq[ni][1]);
                }
                if (v1) {
                    colsum[ni][0] += o2; colsum[ni][1] += o3;
                    colsq[ni][0] = fmaf(o2, o2, colsq[ni][0]);
                    colsq[ni][1] = fmaf(o3, o3, colsq[ni][1]);
                }
            }
        }
    }

    if (MODE == 0) {
        // reduce over the 8 gid values (lanes differing in bits 2,3,4)
#pragma unroll
        for (int ni = 0; ni < 4; ni++)
#pragma unroll
            for (int j = 0; j < 2; j++) {
                float s = colsum[ni][j], q = colsq[ni][j];
#pragma unroll
                for (int off = 4; off < 32; off <<= 1) {
                    s += __shfl_xor_sync(0xFFFFFFFFu, s, off);
                    q += __shfl_xor_sync(0xFFFFFFFFu, q, off);
                }
                if (gid == 0) {
                    int c = wc * 32 + ni * 8 + tig * 2 + j;
                    atomicAdd(&s_stats[c], s);
                    atomicAdd(&s_stats[128 + c], q);
                }
            }
        __syncthreads();
        if (tid < 256) atomicAdd(&g_stats[tid], s_stats[tid]);
    }
}

// -------------------- BN params: fold stats + gamma/beta into a,b --------------------
__global__ void bnparams_kernel(const float* __restrict__ gamma, const float* __restrict__ beta) {
    int j = threadIdx.x;
    if (j < F) {
        float inv_n = 1.0f / (float)N_NODES;
        float mu = g_stats[j] * inv_n;
        float var = g_stats[F + j] * inv_n - mu * mu;
        float a = gamma[j] * rsqrtf(var + BN_EPS);
        g_ab[j] = a;
        g_ab[F + j] = fmaf(-mu, a, beta[j]);
    }
}

// -------------------- launch --------------------
extern "C" void kernel_launch(void* const* d_in, const int* in_sizes, int n_in,
                              void* d_out, int out_size) {
    const float* x     = (const float*)d_in[0];
    const void*  ei    = d_in[1];
    const float* eps   = (const float*)d_in[2];
    const float* W1    = (const float*)d_in[3];
    const float* b1    = (const float*)d_in[4];
    const float* gamma = (const float*)d_in[5];
    const float* beta  = (const float*)d_in[6];
    const float* W2    = (const float*)d_in[7];
    const float* b2    = (const float*)d_in[8];
    float* out = (float*)d_out;

    float *h_ptr, *h1_ptr;
    cudaGetSymbolAddress((void**)&h_ptr, g_h);
    cudaGetSymbolAddress((void**)&h1_ptr, g_h1);

    const int smem_bytes = 4 * TILE_ELEMS * 2 + (128 + 256 + 256) * 4;
    cudaFuncSetAttribute(gemm_mma_kernel<0>, cudaFuncAttributeMaxDynamicSharedMemorySize, smem_bytes);
    cudaFuncSetAttribute(gemm_mma_kernel<1>, cudaFuncAttributeMaxDynamicSharedMemorySize, smem_bytes);

    // 0) detect edge_index dtype (int32 vs int64)
    detect_kernel<<<1, 32>>>((const int*)ei);

    // 1) h = (1+eps)*x ; zero stats
    init_kernel<<<2048, 256>>>(x, eps);

    // 2) scatter-add neighbors: h[row] += x[col]  (warp per edge)
    scatter_kernel<<<(NE * 32) / 256, 256>>>(ei, x);

    // 3) h1 = h @ W1^T + b1 (+ stats)   [mma.sync bf16 split, ldmatrix]
    int gblocks = (N_NODES + 127) / 128;
    gemm_mma_kernel<0><<<gblocks, 512, smem_bytes>>>(h_ptr, W1, b1, h1_ptr, N_NODES);

    // 4) fold BN params
    bnparams_kernel<<<1, 128>>>(gamma, beta);

    // 5) out = relu(bn(h1)) @ W2^T + b2   [mma.sync bf16 split, ldmatrix]
    gemm_mma_kernel<1><<<gblocks, 512, smem_bytes>>>(h1_ptr, W2, b2, out, N_NODES);
}

// round 11
// speedup vs baseline: 1.9289x; 1.4745x over previous
#include <cuda_runtime.h>
#include <cuda_bf16.h>
#include <cstdint>

#define N_NODES 100000
#define F 128
#define NE 1600000
#define BN_EPS 1e-5f
#define SCAN_BLKS 391   // ceil(N_NODES / 256)

// Scratch (no allocations allowed) — __device__ globals.
__device__ float g_h[N_NODES * F];    // (1+eps)x + agg
__device__ float g_h1[N_NODES * F];   // after Linear1
__device__ float g_stats[2 * F];      // [0..127] sum, [128..255] sumsq
__device__ float g_ab[2 * F];         // a = gamma*rsqrt(var+eps), b = beta - mu*a
__device__ int   g_is64;              // 1 if edge_index stored as int64, 0 if int32
__device__ int   g_off[N_NODES + 1];  // CSR row offsets
__device__ int   g_cur[N_NODES];      // degree counter / fill cursor
__device__ int   g_idx[NE];           // CSR column (source node) indices
__device__ int   g_bsum[SCAN_BLKS + 1];

// -------------------- dtype detection for edge_index --------------------
__global__ void detect_kernel(const int* __restrict__ ei32) {
    if (threadIdx.x == 0 && blockIdx.x == 0) {
        int nz = 0;
        for (int i = 1; i < 256; i += 2) nz |= ei32[i];
        g_is64 = (nz == 0) ? 1 : 0;
    }
}

// -------------------- CSR build --------------------
__global__ void zero_kernel() {
    int i = blockIdx.x * blockDim.x + threadIdx.x;
    if (i < N_NODES) g_cur[i] = 0;
    if (i < 2 * F) g_stats[i] = 0.0f;
}

__global__ void hist_kernel(const void* __restrict__ ei_raw) {
    int e = blockIdx.x * blockDim.x + threadIdx.x;
    if (e >= NE) return;
    int dst;
    if (g_is64) dst = (int)((const long long*)ei_raw)[e];
    else        dst = ((const int*)ei_raw)[e];
    if ((unsigned)dst < N_NODES) atomicAdd(&g_cur[dst], 1);
}

__global__ void blocksum_kernel() {
    __shared__ int sc[256];
    int t = threadIdx.x;
    int i = blockIdx.x * 256 + t;
    sc[t] = (i < N_NODES) ? g_cur[i] : 0;
    __syncthreads();
    for (int off = 128; off; off >>= 1) {
        if (t < off) sc[t] += sc[t + off];
        __syncthreads();
    }
    if (t == 0) g_bsum[blockIdx.x] = sc[0];
}

__global__ void scanb_kernel() {
    __shared__ int sc[512];
    int t = threadIdx.x;
    sc[t] = (t < SCAN_BLKS) ? g_bsum[t] : 0;
    __syncthreads();
    for (int off = 1; off < 512; off <<= 1) {
        int v = (t >= off) ? sc[t - off] : 0;
        __syncthreads();
        sc[t] += v;
        __syncthreads();
    }
    if (t < SCAN_BLKS) g_bsum[t] = sc[t] - ((t < SCAN_BLKS) ? ((t == 0) ? sc[0] : sc[t] - sc[t - 1]) : 0) * 0
                                   - ((t == 0) ? sc[0] : sc[t] - sc[t - 1]);  // exclusive = incl - own
    // simpler: exclusive[t] = (t==0) ? 0 : sc[t-1]
    __syncthreads();
    if (t < SCAN_BLKS) g_bsum[t] = (t == 0) ? 0 : sc[t - 1];
}

__global__ void offsets_kernel() {
    __shared__ int sc[256];
    int t = threadIdx.x;
    int i = blockIdx.x * 256 + t;
    int d = (i < N_NODES) ? g_cur[i] : 0;
    sc[t] = d;
    __syncthreads();
    for (int off = 1; off < 256; off <<= 1) {
        int v = (t >= off) ? sc[t - off] : 0;
        __syncthreads();
        sc[t] += v;
        __syncthreads();
    }
    int excl = sc[t] - d;
    int o = g_bsum[blockIdx.x] + excl;
    if (i < N_NODES) {
        g_off[i] = o;
        g_cur[i] = o;
        if (i == N_NODES - 1) g_off[N_NODES] = o + d;
    }
}

__global__ void fill_kernel(const void* __restrict__ ei_raw) {
    int e = blockIdx.x * blockDim.x + threadIdx.x;
    if (e >= NE) return;
    int dst, src;
    if (g_is64) {
        const long long* ei = (const long long*)ei_raw;
        dst = (int)ei[e];
        src = (int)ei[NE + e];
    } else {
        const int* ei = (const int*)ei_raw;
        dst = ei[e];
        src = ei[NE + e];
    }
    if ((unsigned)dst >= N_NODES || (unsigned)src >= N_NODES) return;
    int pos = atomicAdd(&g_cur[dst], 1);
    g_idx[pos] = src;
}

// -------------------- aggregate (fused init): h[n] = (1+eps)x[n] + sum_j x[idx[j]] --------------------
__global__ void agg_kernel(const float* __restrict__ x, const float* __restrict__ eps) {
    int warp = (blockIdx.x * blockDim.x + threadIdx.x) >> 5;
    if (warp >= N_NODES) return;
    int lane = threadIdx.x & 31;
    const float4* x4 = (const float4*)x;
    float s = 1.0f + eps[0];
    float4 a = x4[(size_t)warp * 32 + lane];
    float ax = a.x * s, ay = a.y * s, az = a.z * s, aw = a.w * s;

    int j = g_off[warp], end = g_off[warp + 1];
    for (; j + 4 <= end; j += 4) {
        int s0 = g_idx[j], s1 = g_idx[j + 1], s2 = g_idx[j + 2], s3 = g_idx[j + 3];
        float4 v0 = x4[(size_t)s0 * 32 + lane];
        float4 v1 = x4[(size_t)s1 * 32 + lane];
        float4 v2 = x4[(size_t)s2 * 32 + lane];
        float4 v3 = x4[(size_t)s3 * 32 + lane];
        ax += v0.x + v1.x + v2.x + v3.x;
        ay += v0.y + v1.y + v2.y + v3.y;
        az += v0.z + v1.z + v2.z + v3.z;
        aw += v0.w + v1.w + v2.w + v3.w;
    }
    for (; j < end; j++) {
        float4 v = x4[(size_t)g_idx[j] * 32 + lane];
        ax += v.x; ay += v.y; az += v.z; aw += v.w;
    }
    ((float4*)g_h)[(size_t)warp * 32 + lane] = make_float4(ax, ay, az, aw);
}

// -------------------- HMMA / ldmatrix helpers --------------------
__device__ __forceinline__ void mma_bf16(float* c, uint32_t a0, uint32_t a1, uint32_t a2, uint32_t a3,
                                         uint32_t b0, uint32_t b1) {
    asm volatile(
        "mma.sync.aligned.m16n8k16.row.col.f32.bf16.bf16.f32 "
        "{%0,%1,%2,%3}, {%4,%5,%6,%7}, {%8,%9}, {%0,%1,%2,%3};"
        : "+f"(c[0]), "+f"(c[1]), "+f"(c[2]), "+f"(c[3])
        : "r"(a0), "r"(a1), "r"(a2), "r"(a3), "r"(b0), "r"(b1));
}
#define LDSM_X4(r0, r1, r2, r3, addr) \
    asm volatile("ldmatrix.sync.aligned.m8n8.x4.shared.b16 {%0,%1,%2,%3}, [%4];" \
                 : "=r"(r0), "=r"(r1), "=r"(r2), "=r"(r3) : "r"(addr))

__device__ __forceinline__ uint32_t smem_u32(const void* p) {
    uint32_t a;
    asm("{ .reg .u64 t; cvta.to.shared.u64 t, %1; cvt.u32.u64 %0, t; }" : "=r"(a) : "l"(p));
    return a;
}

// smem tile geometry: [128 rows][136 bf16] (272B row stride: 16B-aligned, conflict-free)
#define TSTRIDE 136
#define TILE_ELEMS (128 * TSTRIDE)

// -------------------- mma GEMM: out = A' @ W^T + bias --------------------
template<int MODE>
__global__ __launch_bounds__(512, 1) void gemm_mma_kernel(
    const float* __restrict__ A, const float* __restrict__ W,
    const float* __restrict__ bias, float* __restrict__ out, int nrows)
{
    extern __shared__ char smem[];
    __nv_bfloat16* sAh = (__nv_bfloat16*)smem;
    __nv_bfloat16* sAl = sAh + TILE_ELEMS;
    __nv_bfloat16* sBh = sAl + TILE_ELEMS;
    __nv_bfloat16* sBl = sBh + TILE_ELEMS;
    float* s_bias  = (float*)(sBl + TILE_ELEMS);
    float* s_ab    = s_bias + 128;
    float* s_stats = s_ab + 256;

    const int tid = threadIdx.x;
    const int wid = tid >> 5;
    const int lane = tid & 31;
    const int gid = lane >> 2;
    const int tig = lane & 3;
    const int wr = wid >> 2;
    const int wc = wid & 3;
    const int rbase = blockIdx.x * 128;

    if (tid < 128) s_bias[tid] = bias[tid];
    if (MODE == 1 && tid < 256) s_ab[tid] = g_ab[tid];
    if (MODE == 0 && tid < 256) s_stats[tid] = 0.0f;
    __syncthreads();

    // ---- convert W -> sBh/sBl ----
    for (int idx = tid; idx < 128 * 32; idx += 512) {
        int c = idx >> 5, q = idx & 31;
        int k = q * 4;
        float4 v = *(const float4*)&W[c * F + k];
        __nv_bfloat16 h0 = __float2bfloat16(v.x), h1 = __float2bfloat16(v.y);
        __nv_bfloat16 h2 = __float2bfloat16(v.z), h3 = __float2bfloat16(v.w);
        __nv_bfloat16 l0 = __float2bfloat16(v.x - __bfloat162float(h0));
        __nv_bfloat16 l1 = __float2bfloat16(v.y - __bfloat162float(h1));
        __nv_bfloat16 l2 = __float2bfloat16(v.z - __bfloat162float(h2));
        __nv_bfloat16 l3 = __float2bfloat16(v.w - __bfloat162float(h3));
        *(__nv_bfloat162*)&sBh[c * TSTRIDE + k]     = __nv_bfloat162(h0, h1);
        *(__nv_bfloat162*)&sBh[c * TSTRIDE + k + 2] = __nv_bfloat162(h2, h3);
        *(__nv_bfloat162*)&sBl[c * TSTRIDE + k]     = __nv_bfloat162(l0, l1);
        *(__nv_bfloat162*)&sBl[c * TSTRIDE + k + 2] = __nv_bfloat162(l2, l3);
    }
    // ---- convert A tile -> sAh/sAl (with MODE-1 BN+ReLU) ----
    for (int idx = tid; idx < 128 * 32; idx += 512) {
        int r = idx >> 5, q = idx & 31;
        int k = q * 4;
        int gr = rbase + r;
        float4 v = make_float4(0.f, 0.f, 0.f, 0.f);
        if (gr < nrows) {
            v = *(const float4*)&A[(size_t)gr * F + k];
            if (MODE == 1) {
                v.x = fmaxf(fmaf(v.x, s_ab[k + 0], s_ab[F + k + 0]), 0.0f);
                v.y = fmaxf(fmaf(v.y, s_ab[k + 1], s_ab[F + k + 1]), 0.0f);
                v.z = fmaxf(fmaf(v.z, s_ab[k + 2], s_ab[F + k + 2]), 0.0f);
                v.w = fmaxf(fmaf(v.w, s_ab[k + 3], s_ab[F + k + 3]), 0.0f);
            }
        }
        __nv_bfloat16 h0 = __float2bfloat16(v.x), h1 = __float2bfloat16(v.y);
        __nv_bfloat16 h2 = __float2bfloat16(v.z), h3 = __float2bfloat16(v.w);
        __nv_bfloat16 l0 = __float2bfloat16(v.x - __bfloat162float(h0));
        __nv_bfloat16 l1 = __float2bfloat16(v.y - __bfloat162float(h1));
        __nv_bfloat16 l2 = __float2bfloat16(v.z - __bfloat162float(h2));
        __nv_bfloat16 l3 = __float2bfloat16(v.w - __bfloat162float(h3));
        *(__nv_bfloat162*)&sAh[r * TSTRIDE + k]     = __nv_bfloat162(h0, h1);
        *(__nv_bfloat162*)&sAh[r * TSTRIDE + k + 2] = __nv_bfloat162(h2, h3);
        *(__nv_bfloat162*)&sAl[r * TSTRIDE + k]     = __nv_bfloat162(l0, l1);
        *(__nv_bfloat162*)&sAl[r * TSTRIDE + k + 2] = __nv_bfloat162(l2, l3);
    }
    __syncthreads();

    const int a_off = (((lane >> 3) & 1) * 8 + (lane & 7)) * TSTRIDE + ((lane >> 4) & 1) * 8;
    const int b_off = (((lane >> 4) & 1) * 8 + (lane & 7)) * TSTRIDE + ((lane >> 3) & 1) * 8;

    const uint32_t sAh_u = smem_u32(sAh), sAl_u = smem_u32(sAl);
    const uint32_t sBh_u = smem_u32(sBh), sBl_u = smem_u32(sBl);

    float acc[2][4][4];
#pragma unroll
    for (int mi = 0; mi < 2; mi++)
#pragma unroll
        for (int ni = 0; ni < 4; ni++)
#pragma unroll
            for (int j = 0; j < 4; j++) acc[mi][ni][j] = 0.0f;

    const uint32_t aBase[3] = {sAh_u, sAh_u, sAl_u};
    const uint32_t bBase[3] = {sBh_u, sBl_u, sBh_u};

#pragma unroll
    for (int s = 0; s < 3; s++) {
        const uint32_t sa = aBase[s] + 2 * (wr * 32 * TSTRIDE + a_off);
        const uint32_t sb = bBase[s] + 2 * (wc * 32 * TSTRIDE + b_off);
#pragma unroll
        for (int ks = 0; ks < 8; ks++) {
            const uint32_t kb = 2 * (ks * 16);
            uint32_t af[2][4];
            LDSM_X4(af[0][0], af[0][1], af[0][2], af[0][3], sa + kb);
            LDSM_X4(af[1][0], af[1][1], af[1][2], af[1][3], sa + 2 * (16 * TSTRIDE) + kb);
            uint32_t bf[4][2];
            LDSM_X4(bf[0][0], bf[0][1], bf[1][0], bf[1][1], sb + kb);
            LDSM_X4(bf[2][0], bf[2][1], bf[3][0], bf[3][1], sb + 2 * (16 * TSTRIDE) + kb);
#pragma unroll
            for (int mi = 0; mi < 2; mi++)
#pragma unroll
                for (int ni = 0; ni < 4; ni++)
                    mma_bf16(acc[mi][ni], af[mi][0], af[mi][1], af[mi][2], af[mi][3],
                             bf[ni][0], bf[ni][1]);
        }
    }

    float bsv[4][2];
#pragma unroll
    for (int ni = 0; ni < 4; ni++) {
        int c = wc * 32 + ni * 8 + tig * 2;
        bsv[ni][0] = s_bias[c];
        bsv[ni][1] = s_bias[c + 1];
    }

    float colsum[4][2], colsq[4][2];
#pragma unroll
    for (int ni = 0; ni < 4; ni++) {
        colsum[ni][0] = colsum[ni][1] = 0.0f;
        colsq[ni][0] = colsq[ni][1] = 0.0f;
    }

#pragma unroll
    for (int mi = 0; mi < 2; mi++) {
        int r0 = rbase + wr * 32 + mi * 16 + gid;
        int r1 = r0 + 8;
        bool v0 = (r0 < nrows), v1 = (r1 < nrows);
#pragma unroll
        for (int ni = 0; ni < 4; ni++) {
            int c = wc * 32 + ni * 8 + tig * 2;
            float o0 = acc[mi][ni][0] + bsv[ni][0];
            float o1 = acc[mi][ni][1] + bsv[ni][1];
            float o2 = acc[mi][ni][2] + bsv[ni][0];
            float o3 = acc[mi][ni][3] + bsv[ni][1];
            if (v0) *(float2*)&out[(size_t)r0 * F + c] = make_float2(o0, o1);
            if (v1) *(float2*)&out[(size_t)r1 * F + c] = make_float2(o2, o3);
            if (MODE == 0) {
                if (v0) {
                    colsum[ni][0] += o0; colsum[ni][1] += o1;
                    colsq[ni][0] = fmaf(o0, o0, colsq[ni][0]);
                    colsq[ni][1] = fmaf(o1, o1, colsq[ni][1]);
                }
                if (v1) {
                    colsum[ni][0] += o2; colsum[ni][1] += o3;
                    colsq[ni][0] = fmaf(o2, o2, colsq[ni][0]);
                    colsq[ni][1] = fmaf(o3, o3, colsq[ni][1]);
                }
            }
        }
    }

    if (MODE == 0) {
#pragma unroll
        for (int ni = 0; ni < 4; ni++)
#pragma unroll
            for (int j = 0; j < 2; j++) {
                float s = colsum[ni][j], q = colsq[ni][j];
#pragma unroll
                for (int off = 4; off < 32; off <<= 1) {
                    s += __shfl_xor_sync(0xFFFFFFFFu, s, off);
                    q += __shfl_xor_sync(0xFFFFFFFFu, q, off);
                }
                if (gid == 0) {
                    int c = wc * 32 + ni * 8 + tig * 2 + j;
                    atomicAdd(&s_stats[c], s);
                    atomicAdd(&s_stats[128 + c], q);
                }
            }
        __syncthreads();
        if (tid < 256) atomicAdd(&g_stats[tid], s_stats[tid]);
    }
}

// -------------------- BN params --------------------
__global__ void bnparams_kernel(const float* __restrict__ gamma, const float* __restrict__ beta) {
    int j = threadIdx.x;
    if (j < F) {
        float inv_n = 1.0f / (float)N_NODES;
        float mu = g_stats[j] * inv_n;
        float var = g_stats[F + j] * inv_n - mu * mu;
        float a = gamma[j] * rsqrtf(var + BN_EPS);
        g_ab[j] = a;
        g_ab[F + j] = fmaf(-mu, a, beta[j]);
    }
}

// -------------------- launch --------------------
extern "C" void kernel_launch(void* const* d_in, const int* in_sizes, int n_in,
                              void* d_out, int out_size) {
    const float* x     = (const float*)d_in[0];
    const void*  ei    = d_in[1];
    const float* eps   = (const float*)d_in[2];
    const float* W1    = (const float*)d_in[3];
    const float* b1    = (const float*)d_in[4];
    const float* gamma = (const float*)d_in[5];
    const float* beta  = (const float*)d_in[6];
    const float* W2    = (const float*)d_in[7];
    const float* b2    = (const float*)d_in[8];
    float* out = (float*)d_out;

    float *h_ptr, *h1_ptr;
    cudaGetSymbolAddress((void**)&h_ptr, g_h);
    cudaGetSymbolAddress((void**)&h1_ptr, g_h1);

    const int smem_bytes = 4 * TILE_ELEMS * 2 + (128 + 256 + 256) * 4;
    cudaFuncSetAttribute(gemm_mma_kernel<0>, cudaFuncAttributeMaxDynamicSharedMemorySize, smem_bytes);
    cudaFuncSetAttribute(gemm_mma_kernel<1>, cudaFuncAttributeMaxDynamicSharedMemorySize, smem_bytes);

    // 0) detect edge_index dtype
    detect_kernel<<<1, 32>>>((const int*)ei);

    // 1) CSR build
    zero_kernel<<<SCAN_BLKS, 256>>>();
    hist_kernel<<<(NE + 255) / 256, 256>>>(ei);
    blocksum_kernel<<<SCAN_BLKS, 256>>>();
    scanb_kernel<<<1, 512>>>();
    offsets_kernel<<<SCAN_BLKS, 256>>>();
    fill_kernel<<<(NE + 255) / 256, 256>>>(ei);

    // 2) aggregate + init fused: h = (1+eps)x + sum_neighbors x
    agg_kernel<<<(N_NODES * 32 + 255) / 256, 256>>>(x, eps);

    // 3) h1 = h @ W1^T + b1 (+ stats)
    int gblocks = (N_NODES + 127) / 128;
    gemm_mma_kernel<0><<<gblocks, 512, smem_bytes>>>(h_ptr, W1, b1, h1_ptr, N_NODES);

    // 4) fold BN params
    bnparams_kernel<<<1, 128>>>(gamma, beta);

    // 5) out = relu(bn(h1)) @ W2^T + b2
    gemm_mma_kernel<1><<<gblocks, 512, smem_bytes>>>(h1_ptr, W2, b2, out, N_NODES);
}